// round 1
// baseline (speedup 1.0000x reference)
#include <cuda_runtime.h>
#include <cuda_bf16.h>
#include <math.h>

// Problem constants
#define B_  2
#define S_  2048
#define H_  4096
#define NH_ 32
#define NKV_ 8
#define HD_ 128
#define M_  (B_ * S_)          // 4096 rows
#define QN_ (NH_ * HD_)        // 4096
#define KN_ (NKV_ * HD_)       // 1024

// Scratch (device globals; no allocations allowed)
__device__ float g_Q[M_ * QN_];    // 64 MB
__device__ float g_K[M_ * KN_];    // 16 MB
__device__ float g_V[M_ * KN_];    // 16 MB
__device__ float g_AO[M_ * QN_];   // 64 MB

// ---------------------------------------------------------------------------
// Classic 128x128x8 register-blocked SGEMM: C = A[MxK] @ B[KxN] (+ bias)
// 256 threads, each computes an 8x8 tile.
// ---------------------------------------------------------------------------
__global__ __launch_bounds__(256)
void sgemm128(const float* __restrict__ A, const float* __restrict__ B,
              const float* __restrict__ bias, float* __restrict__ C,
              int M, int N, int K)
{
    __shared__ float As[8][128];
    __shared__ float Bs[8][128];

    const int tid  = threadIdx.x;
    const int brow = blockIdx.y * 128;
    const int bcol = blockIdx.x * 128;

    // A tile load: thread -> (row, 4 cols)
    const int a_r = tid >> 1;
    const int a_c = (tid & 1) * 4;
    // B tile load: thread -> (row, 4 cols)
    const int b_r = tid >> 5;
    const int b_c = (tid & 31) * 4;

    const int tr = (tid / 16) * 8;   // output sub-tile row
    const int tc = (tid % 16) * 8;   // output sub-tile col

    float acc[8][8];
#pragma unroll
    for (int i = 0; i < 8; i++)
#pragma unroll
        for (int j = 0; j < 8; j++) acc[i][j] = 0.f;

    const float* Aptr = A + (size_t)(brow + a_r) * K + a_c;
    const float* Bptr = B + (size_t)b_r * N + bcol + b_c;

    for (int k0 = 0; k0 < K; k0 += 8) {
        float4 av = *(const float4*)(Aptr + k0);
        float4 bv = *(const float4*)(Bptr + (size_t)k0 * N);
        As[a_c + 0][a_r] = av.x;
        As[a_c + 1][a_r] = av.y;
        As[a_c + 2][a_r] = av.z;
        As[a_c + 3][a_r] = av.w;
        *(float4*)&Bs[b_r][b_c] = bv;
        __syncthreads();

#pragma unroll
        for (int kk = 0; kk < 8; kk++) {
            float4 a0 = *(const float4*)&As[kk][tr];
            float4 a1 = *(const float4*)&As[kk][tr + 4];
            float4 b0 = *(const float4*)&Bs[kk][tc];
            float4 b1 = *(const float4*)&Bs[kk][tc + 4];
            float ar[8] = {a0.x, a0.y, a0.z, a0.w, a1.x, a1.y, a1.z, a1.w};
            float br[8] = {b0.x, b0.y, b0.z, b0.w, b1.x, b1.y, b1.z, b1.w};
#pragma unroll
            for (int i = 0; i < 8; i++)
#pragma unroll
                for (int j = 0; j < 8; j++)
                    acc[i][j] += ar[i] * br[j];
        }
        __syncthreads();
    }

    float bcache[8];
#pragma unroll
    for (int j = 0; j < 8; j++)
        bcache[j] = bias ? bias[bcol + tc + j] : 0.f;

#pragma unroll
    for (int i = 0; i < 8; i++) {
        float* Crow = C + (size_t)(brow + tr + i) * N + bcol + tc;
#pragma unroll
        for (int j = 0; j < 8; j += 4) {
            float4 v;
            v.x = acc[i][j + 0] + bcache[j + 0];
            v.y = acc[i][j + 1] + bcache[j + 1];
            v.z = acc[i][j + 2] + bcache[j + 2];
            v.w = acc[i][j + 3] + bcache[j + 3];
            *(float4*)(Crow + j) = v;
        }
    }
}

// ---------------------------------------------------------------------------
// RoPE: in-place on Q (32 heads) and K (8 heads). grid = (B*S, 40), 128 thr.
// Llama-style: concat(freqs, freqs), rotate_half.
// ---------------------------------------------------------------------------
__global__ __launch_bounds__(128)
void rope_kernel(float* __restrict__ Q, float* __restrict__ K,
                 const int* __restrict__ pos_ids)
{
    const int row  = blockIdx.x;      // b*S + s
    const int head = blockIdx.y;      // <32 -> Q head, else K head
    const int d    = threadIdx.x;     // 0..127

    const int pos = pos_ids[row];
    const int i = d & 63;
    // inv_freq = 10000^{-(2i)/128}
    const float inv_freq = exp2f(-(float)(2 * i) * (1.0f / 128.0f) * 13.28771238f);
    const float ang = (float)pos * inv_freq;
    float c, s;
    sincosf(ang, &s, &c);

    float* base = (head < NH_)
        ? (Q + (size_t)row * QN_ + head * HD_)
        : (K + (size_t)row * KN_ + (head - NH_) * HD_);

    const float x = base[d];
    const float other = (d < 64) ? -base[d + 64] : base[d - 64];
    const float v = x * c + other * s;
    __syncthreads();   // all reads of the head vector before any writes
    base[d] = v;
}

// ---------------------------------------------------------------------------
// Flash-style fp32 causal attention with GQA.
// grid = (S/16, NH, B); 128 threads/block; 16 queries/block, 64-key tiles.
// Thread t: qi = t/8 (query), lane8 = t%8.
//   QK phase: thread computes scores for j = lane8 + 8*jj (jj=0..7).
//   PV phase: thread accumulates o[qi][d] for d = lane8 + 8*i (i=0..15).
// ---------------------------------------------------------------------------
__global__ __launch_bounds__(128)
void attn_kernel(const float* __restrict__ Q, const float* __restrict__ K,
                 const float* __restrict__ V, float* __restrict__ O)
{
    const int qt = blockIdx.x;
    const int h  = blockIdx.y;
    const int b  = blockIdx.z;
    const int q0 = qt * 16;
    const int kvh = h >> 2;          // repeat_interleave grouping
    const int t = threadIdx.x;
    const int qi = t >> 3;           // 0..15
    const int lane8 = t & 7;

    __shared__ float Qs[16][129];
    __shared__ float KVs[64][129];
    __shared__ float Ps[16][65];

    const float scale = 0.08838834764831845f;   // 1/sqrt(128)
    const float NEG_INF = -INFINITY;

    // load Q tile (scaled)
    for (int idx = t; idx < 16 * 128; idx += 128) {
        const int r = idx >> 7, c = idx & 127;
        Qs[r][c] = Q[(size_t)(b * S_ + q0 + r) * QN_ + h * HD_ + c] * scale;
    }

    float m = NEG_INF, l = 0.f;
    float o[16];
#pragma unroll
    for (int i = 0; i < 16; i++) o[i] = 0.f;

    const int qg = q0 + qi;          // global query index (== position)
    const int numK = q0 + 16;        // causal horizon for this block

    for (int kt = 0; kt * 64 < numK; kt++) {
        __syncthreads();             // protect KVs/Ps from previous iteration
        const int kbase = kt * 64;
        const int kn = min(64, numK - kbase);

        // load K tile
        for (int idx = t; idx < kn * 128; idx += 128) {
            const int r = idx >> 7, c = idx & 127;
            KVs[r][c] = K[(size_t)(b * S_ + kbase + r) * KN_ + kvh * HD_ + c];
        }
        __syncthreads();

        // scores: s[jj] = dot(Qs[qi], KVs[lane8 + 8*jj])
        float s[8];
#pragma unroll
        for (int jj = 0; jj < 8; jj++) s[jj] = 0.f;
#pragma unroll 4
        for (int c = 0; c < 128; c++) {
            const float qv = Qs[qi][c];
#pragma unroll
            for (int jj = 0; jj < 8; jj++)
                s[jj] += qv * KVs[lane8 + jj * 8][c];
        }
        // causal + ragged mask
#pragma unroll
        for (int jj = 0; jj < 8; jj++) {
            const int j = lane8 + jj * 8;
            if (j >= kn || kbase + j > qg) s[jj] = NEG_INF;
        }

        // online softmax over the 8-lane query group
        float mt = s[0];
#pragma unroll
        for (int jj = 1; jj < 8; jj++) mt = fmaxf(mt, s[jj]);
#pragma unroll
        for (int off = 1; off < 8; off <<= 1)
            mt = fmaxf(mt, __shfl_xor_sync(0xffffffffu, mt, off));

        const float newm = fmaxf(m, mt);
        const float alpha = expf(m - newm);   // m=-inf first tile -> 0

        float rs = 0.f;
#pragma unroll
        for (int jj = 0; jj < 8; jj++) {
            const float p = expf(s[jj] - newm);
            Ps[qi][lane8 + jj * 8] = p;
            rs += p;
        }
#pragma unroll
        for (int off = 1; off < 8; off <<= 1)
            rs += __shfl_xor_sync(0xffffffffu, rs, off);

        l = l * alpha + rs;
        m = newm;
#pragma unroll
        for (int i = 0; i < 16; i++) o[i] *= alpha;

        __syncthreads();             // everyone done reading K, Ps written

        // load V tile (overwrites K tile)
        for (int idx = t; idx < kn * 128; idx += 128) {
            const int r = idx >> 7, c = idx & 127;
            KVs[r][c] = V[(size_t)(b * S_ + kbase + r) * KN_ + kvh * HD_ + c];
        }
        __syncthreads();

        // PV: o[d] += sum_j p[j] * V[j][d],  d = lane8 + 8*i
        for (int j = 0; j < kn; j++) {
            const float p = Ps[qi][j];
#pragma unroll
            for (int i = 0; i < 16; i++)
                o[i] += p * KVs[j][lane8 + i * 8];
        }
    }

    const float inv_l = 1.f / l;
    float* Orow = O + (size_t)(b * S_ + q0 + qi) * QN_ + h * HD_;
#pragma unroll
    for (int i = 0; i < 16; i++)
        Orow[lane8 + i * 8] = o[i] * inv_l;
}

// ---------------------------------------------------------------------------
// Launcher
// ---------------------------------------------------------------------------
extern "C" void kernel_launch(void* const* d_in, const int* in_sizes, int n_in,
                              void* d_out, int out_size)
{
    const float* X   = (const float*)d_in[0];
    const int*   pos = (const int*)  d_in[1];
    const float* Wq  = (const float*)d_in[2];
    const float* bq  = (const float*)d_in[3];
    const float* Wk  = (const float*)d_in[4];
    const float* bk  = (const float*)d_in[5];
    const float* Wv  = (const float*)d_in[6];
    const float* bv  = (const float*)d_in[7];
    const float* Wo  = (const float*)d_in[8];
    float* out = (float*)d_out;

    float *Qb, *Kb, *Vb, *AOb;
    cudaGetSymbolAddress((void**)&Qb,  g_Q);
    cudaGetSymbolAddress((void**)&Kb,  g_K);
    cudaGetSymbolAddress((void**)&Vb,  g_V);
    cudaGetSymbolAddress((void**)&AOb, g_AO);

    // QKV projections
    sgemm128<<<dim3(QN_ / 128, M_ / 128), 256>>>(X, Wq, bq, Qb, M_, QN_, H_);
    sgemm128<<<dim3(KN_ / 128, M_ / 128), 256>>>(X, Wk, bk, Kb, M_, KN_, H_);
    sgemm128<<<dim3(KN_ / 128, M_ / 128), 256>>>(X, Wv, bv, Vb, M_, KN_, H_);

    // RoPE on Q and K (in-place)
    rope_kernel<<<dim3(M_, NH_ + NKV_), 128>>>(Qb, Kb, pos);

    // Causal GQA attention
    attn_kernel<<<dim3(S_ / 16, NH_, B_), 128>>>(Qb, Kb, Vb, AOb);

    // Output projection
    sgemm128<<<dim3(QN_ / 128, M_ / 128), 256>>>(AOb, Wo, nullptr, out, M_, QN_, H_);
}

// round 2
// speedup vs baseline: 1.7921x; 1.7921x over previous
#include <cuda_runtime.h>
#include <cuda_bf16.h>
#include <math.h>

// Problem constants
#define B_  2
#define S_  2048
#define H_  4096
#define NH_ 32
#define NKV_ 8
#define HD_ 128
#define M_  (B_ * S_)          // 4096 rows
#define QN_ (NH_ * HD_)        // 4096
#define KN_ (NKV_ * HD_)       // 1024

// Scratch (device globals; no allocations allowed)
__device__ float g_Q[M_ * QN_];    // 64 MB
__device__ float g_K[M_ * KN_];    // 16 MB
__device__ float g_V[M_ * KN_];    // 16 MB
__device__ float g_AO[M_ * QN_];   // 64 MB

// ---------------------------------------------------------------------------
// TF32 tensor-core GEMM: C = A[MxK] @ B[KxN] (+ bias)
// 128x128 block tile, 8 warps (each 64x32), k-tile 16, 2-stage cp.async.
// mma.sync.aligned.m16n8k8.row.col.f32.tf32.tf32.f32
// ---------------------------------------------------------------------------
#define AS_STRIDE 20     // 16 cols + pad; (row*20+col)%32 conflict-free for A frags
#define BS_STRIDE 136    // 128 cols + pad; stride%32==8 -> conflict-free for B frags
#define STAGE_FLOATS (128 * AS_STRIDE + 16 * BS_STRIDE)   // 2560+2176=4736 floats

__device__ __forceinline__ unsigned cvt_tf32(float f) {
    unsigned r;
    asm("cvt.rna.tf32.f32 %0, %1;" : "=r"(r) : "f"(f));
    return r;
}

__device__ __forceinline__ void mma_tf32(float& d0, float& d1, float& d2, float& d3,
                                         unsigned a0, unsigned a1, unsigned a2, unsigned a3,
                                         unsigned b0, unsigned b1)
{
    asm volatile(
        "mma.sync.aligned.m16n8k8.row.col.f32.tf32.tf32.f32 "
        "{%0,%1,%2,%3}, {%4,%5,%6,%7}, {%8,%9}, {%0,%1,%2,%3};"
        : "+f"(d0), "+f"(d1), "+f"(d2), "+f"(d3)
        : "r"(a0), "r"(a1), "r"(a2), "r"(a3), "r"(b0), "r"(b1));
}

__device__ __forceinline__ void cp_async16(void* smem_dst, const void* gsrc) {
    unsigned dst = (unsigned)__cvta_generic_to_shared(smem_dst);
    asm volatile("cp.async.cg.shared.global [%0], [%1], 16;" :: "r"(dst), "l"(gsrc));
}

__global__ __launch_bounds__(256)
void gemm_tf32(const float* __restrict__ A, const float* __restrict__ B,
               const float* __restrict__ bias, float* __restrict__ C,
               int M, int N, int K)
{
    __shared__ float smem[2 * STAGE_FLOATS];

    const int tid  = threadIdx.x;
    const int wid  = tid >> 5;
    const int lane = tid & 31;
    const int warp_m = (wid & 1) * 64;   // 2 warps along M
    const int warp_n = (wid >> 1) * 32;  // 4 warps along N
    const int brow = blockIdx.y * 128;
    const int bcol = blockIdx.x * 128;
    const int lr = lane >> 2;            // 0..7
    const int lc = lane & 3;             // 0..3

    float acc[4][4][4];
#pragma unroll
    for (int mt = 0; mt < 4; mt++)
#pragma unroll
        for (int nt = 0; nt < 4; nt++)
#pragma unroll
            for (int i = 0; i < 4; i++) acc[mt][nt][i] = 0.f;

    // Load index decomposition
    const int a_row0 = tid >> 2;          // 0..63, +64 second pass
    const int a_col  = (tid & 3) * 4;     // 0..12
    const int b_row0 = tid >> 5;          // 0..7,  +8 second pass
    const int b_col  = (tid & 31) * 4;    // 0..124

    auto load_stage = [&](int s, int k0) {
        float* Asm = smem + s * STAGE_FLOATS;
        float* Bsm = Asm + 128 * AS_STRIDE;
#pragma unroll
        for (int it = 0; it < 2; it++) {
            int r = a_row0 + it * 64;
            cp_async16(&Asm[r * AS_STRIDE + a_col],
                       &A[(size_t)(brow + r) * K + k0 + a_col]);
        }
#pragma unroll
        for (int it = 0; it < 2; it++) {
            int r = b_row0 + it * 8;
            cp_async16(&Bsm[r * BS_STRIDE + b_col],
                       &B[(size_t)(k0 + r) * N + bcol + b_col]);
        }
        asm volatile("cp.async.commit_group;");
    };

    const int KT = K / 16;
    load_stage(0, 0);

    for (int kt = 0; kt < KT; kt++) {
        const int s = kt & 1;
        if (kt + 1 < KT) {
            load_stage(s ^ 1, (kt + 1) * 16);
            asm volatile("cp.async.wait_group 1;");
        } else {
            asm volatile("cp.async.wait_group 0;");
        }
        __syncthreads();

        const float* Asm = smem + s * STAGE_FLOATS;
        const float* Bsm = Asm + 128 * AS_STRIDE;

#pragma unroll
        for (int ks = 0; ks < 2; ks++) {
            const int k0 = ks * 8;
            unsigned af[4][4], bf[4][2];
#pragma unroll
            for (int mt = 0; mt < 4; mt++) {
                const float* ap = Asm + (warp_m + mt * 16 + lr) * AS_STRIDE + k0 + lc;
                af[mt][0] = cvt_tf32(ap[0]);                    // (g,    t)
                af[mt][1] = cvt_tf32(ap[8 * AS_STRIDE]);        // (g+8,  t)
                af[mt][2] = cvt_tf32(ap[4]);                    // (g,    t+4)
                af[mt][3] = cvt_tf32(ap[8 * AS_STRIDE + 4]);    // (g+8,  t+4)
            }
#pragma unroll
            for (int nt = 0; nt < 4; nt++) {
                const float* bp = Bsm + (k0 + lc) * BS_STRIDE + warp_n + nt * 8 + lr;
                bf[nt][0] = cvt_tf32(bp[0]);
                bf[nt][1] = cvt_tf32(bp[4 * BS_STRIDE]);
            }
#pragma unroll
            for (int mt = 0; mt < 4; mt++)
#pragma unroll
                for (int nt = 0; nt < 4; nt++)
                    mma_tf32(acc[mt][nt][0], acc[mt][nt][1], acc[mt][nt][2], acc[mt][nt][3],
                             af[mt][0], af[mt][1], af[mt][2], af[mt][3],
                             bf[nt][0], bf[nt][1]);
        }
        __syncthreads();
    }

    // Epilogue
#pragma unroll
    for (int mt = 0; mt < 4; mt++) {
#pragma unroll
        for (int nt = 0; nt < 4; nt++) {
            const int row0 = brow + warp_m + mt * 16 + lr;
            const int col  = bcol + warp_n + nt * 8 + lc * 2;
            const float b0 = bias ? bias[col]     : 0.f;
            const float b1 = bias ? bias[col + 1] : 0.f;
            float2 v0 = make_float2(acc[mt][nt][0] + b0, acc[mt][nt][1] + b1);
            float2 v1 = make_float2(acc[mt][nt][2] + b0, acc[mt][nt][3] + b1);
            *(float2*)&C[(size_t)row0 * N + col]       = v0;
            *(float2*)&C[(size_t)(row0 + 8) * N + col] = v1;
        }
    }
}

// ---------------------------------------------------------------------------
// RoPE: in-place on Q (32 heads) and K (8 heads). grid = (B*S, 40), 128 thr.
// ---------------------------------------------------------------------------
__global__ __launch_bounds__(128)
void rope_kernel(float* __restrict__ Q, float* __restrict__ K,
                 const int* __restrict__ pos_ids)
{
    const int row  = blockIdx.x;
    const int head = blockIdx.y;
    const int d    = threadIdx.x;

    const int pos = pos_ids[row];
    const int i = d & 63;
    const float inv_freq = exp2f(-(float)(2 * i) * (1.0f / 128.0f) * 13.28771238f);
    const float ang = (float)pos * inv_freq;
    float c, s;
    sincosf(ang, &s, &c);

    float* base = (head < NH_)
        ? (Q + (size_t)row * QN_ + head * HD_)
        : (K + (size_t)row * KN_ + (head - NH_) * HD_);

    const float x = base[d];
    const float other = (d < 64) ? -base[d + 64] : base[d - 64];
    const float v = x * c + other * s;
    __syncthreads();
    base[d] = v;
}

// ---------------------------------------------------------------------------
// Flash-style fp32 causal attention with GQA (unchanged from R1).
// ---------------------------------------------------------------------------
__global__ __launch_bounds__(128)
void attn_kernel(const float* __restrict__ Q, const float* __restrict__ K,
                 const float* __restrict__ V, float* __restrict__ O)
{
    const int qt = blockIdx.x;
    const int h  = blockIdx.y;
    const int b  = blockIdx.z;
    const int q0 = qt * 16;
    const int kvh = h >> 2;
    const int t = threadIdx.x;
    const int qi = t >> 3;
    const int lane8 = t & 7;

    __shared__ float Qs[16][129];
    __shared__ float KVs[64][129];
    __shared__ float Ps[16][65];

    const float scale = 0.08838834764831845f;
    const float NEG_INF = -INFINITY;

    for (int idx = t; idx < 16 * 128; idx += 128) {
        const int r = idx >> 7, c = idx & 127;
        Qs[r][c] = Q[(size_t)(b * S_ + q0 + r) * QN_ + h * HD_ + c] * scale;
    }

    float m = NEG_INF, l = 0.f;
    float o[16];
#pragma unroll
    for (int i = 0; i < 16; i++) o[i] = 0.f;

    const int qg = q0 + qi;
    const int numK = q0 + 16;

    for (int kt = 0; kt * 64 < numK; kt++) {
        __syncthreads();
        const int kbase = kt * 64;
        const int kn = min(64, numK - kbase);

        for (int idx = t; idx < kn * 128; idx += 128) {
            const int r = idx >> 7, c = idx & 127;
            KVs[r][c] = K[(size_t)(b * S_ + kbase + r) * KN_ + kvh * HD_ + c];
        }
        __syncthreads();

        float s[8];
#pragma unroll
        for (int jj = 0; jj < 8; jj++) s[jj] = 0.f;
#pragma unroll 4
        for (int c = 0; c < 128; c++) {
            const float qv = Qs[qi][c];
#pragma unroll
            for (int jj = 0; jj < 8; jj++)
                s[jj] += qv * KVs[lane8 + jj * 8][c];
        }
#pragma unroll
        for (int jj = 0; jj < 8; jj++) {
            const int j = lane8 + jj * 8;
            if (j >= kn || kbase + j > qg) s[jj] = NEG_INF;
        }

        float mt = s[0];
#pragma unroll
        for (int jj = 1; jj < 8; jj++) mt = fmaxf(mt, s[jj]);
#pragma unroll
        for (int off = 1; off < 8; off <<= 1)
            mt = fmaxf(mt, __shfl_xor_sync(0xffffffffu, mt, off));

        const float newm = fmaxf(m, mt);
        const float alpha = expf(m - newm);

        float rs = 0.f;
#pragma unroll
        for (int jj = 0; jj < 8; jj++) {
            const float p = expf(s[jj] - newm);
            Ps[qi][lane8 + jj * 8] = p;
            rs += p;
        }
#pragma unroll
        for (int off = 1; off < 8; off <<= 1)
            rs += __shfl_xor_sync(0xffffffffu, rs, off);

        l = l * alpha + rs;
        m = newm;
#pragma unroll
        for (int i = 0; i < 16; i++) o[i] *= alpha;

        __syncthreads();

        for (int idx = t; idx < kn * 128; idx += 128) {
            const int r = idx >> 7, c = idx & 127;
            KVs[r][c] = V[(size_t)(b * S_ + kbase + r) * KN_ + kvh * HD_ + c];
        }
        __syncthreads();

        for (int j = 0; j < kn; j++) {
            const float p = Ps[qi][j];
#pragma unroll
            for (int i = 0; i < 16; i++)
                o[i] += p * KVs[j][lane8 + i * 8];
        }
    }

    const float inv_l = 1.f / l;
    float* Orow = O + (size_t)(b * S_ + q0 + qi) * QN_ + h * HD_;
#pragma unroll
    for (int i = 0; i < 16; i++)
        Orow[lane8 + i * 8] = o[i] * inv_l;
}

// ---------------------------------------------------------------------------
// Launcher
// ---------------------------------------------------------------------------
extern "C" void kernel_launch(void* const* d_in, const int* in_sizes, int n_in,
                              void* d_out, int out_size)
{
    const float* X   = (const float*)d_in[0];
    const int*   pos = (const int*)  d_in[1];
    const float* Wq  = (const float*)d_in[2];
    const float* bq  = (const float*)d_in[3];
    const float* Wk  = (const float*)d_in[4];
    const float* bk  = (const float*)d_in[5];
    const float* Wv  = (const float*)d_in[6];
    const float* bv  = (const float*)d_in[7];
    const float* Wo  = (const float*)d_in[8];
    float* out = (float*)d_out;

    float *Qb, *Kb, *Vb, *AOb;
    cudaGetSymbolAddress((void**)&Qb,  g_Q);
    cudaGetSymbolAddress((void**)&Kb,  g_K);
    cudaGetSymbolAddress((void**)&Vb,  g_V);
    cudaGetSymbolAddress((void**)&AOb, g_AO);

    // QKV projections (tf32 tensor cores)
    gemm_tf32<<<dim3(QN_ / 128, M_ / 128), 256>>>(X, Wq, bq, Qb, M_, QN_, H_);
    gemm_tf32<<<dim3(KN_ / 128, M_ / 128), 256>>>(X, Wk, bk, Kb, M_, KN_, H_);
    gemm_tf32<<<dim3(KN_ / 128, M_ / 128), 256>>>(X, Wv, bv, Vb, M_, KN_, H_);

    // RoPE on Q and K (in-place)
    rope_kernel<<<dim3(M_, NH_ + NKV_), 128>>>(Qb, Kb, pos);

    // Causal GQA attention
    attn_kernel<<<dim3(S_ / 16, NH_, B_), 128>>>(Qb, Kb, Vb, AOb);

    // Output projection (tf32 tensor cores)
    gemm_tf32<<<dim3(QN_ / 128, M_ / 128), 256>>>(AOb, Wo, nullptr, out, M_, QN_, H_);
}

// round 3
// speedup vs baseline: 4.0837x; 2.2787x over previous
#include <cuda_runtime.h>
#include <cuda_bf16.h>
#include <math.h>

// Problem constants
#define B_  2
#define S_  2048
#define H_  4096
#define NH_ 32
#define NKV_ 8
#define HD_ 128
#define M_  (B_ * S_)          // 4096 rows
#define QN_ (NH_ * HD_)        // 4096
#define KN_ (NKV_ * HD_)       // 1024

// Scratch (device globals; no allocations allowed)
__device__ float g_Q[M_ * QN_];    // 64 MB
__device__ float g_K[M_ * KN_];    // 16 MB
__device__ float g_V[M_ * KN_];    // 16 MB
__device__ float g_AO[M_ * QN_];   // 64 MB

// ---------------------------------------------------------------------------
// TF32 tensor-core GEMM (unchanged from R2)
// ---------------------------------------------------------------------------
#define AS_STRIDE 20
#define BS_STRIDE 136
#define STAGE_FLOATS (128 * AS_STRIDE + 16 * BS_STRIDE)

__device__ __forceinline__ unsigned cvt_tf32(float f) {
    unsigned r;
    asm("cvt.rna.tf32.f32 %0, %1;" : "=r"(r) : "f"(f));
    return r;
}

__device__ __forceinline__ void mma_tf32(float& d0, float& d1, float& d2, float& d3,
                                         unsigned a0, unsigned a1, unsigned a2, unsigned a3,
                                         unsigned b0, unsigned b1)
{
    asm volatile(
        "mma.sync.aligned.m16n8k8.row.col.f32.tf32.tf32.f32 "
        "{%0,%1,%2,%3}, {%4,%5,%6,%7}, {%8,%9}, {%0,%1,%2,%3};"
        : "+f"(d0), "+f"(d1), "+f"(d2), "+f"(d3)
        : "r"(a0), "r"(a1), "r"(a2), "r"(a3), "r"(b0), "r"(b1));
}

__device__ __forceinline__ void cp_async16(void* smem_dst, const void* gsrc) {
    unsigned dst = (unsigned)__cvta_generic_to_shared(smem_dst);
    asm volatile("cp.async.cg.shared.global [%0], [%1], 16;" :: "r"(dst), "l"(gsrc));
}

__global__ __launch_bounds__(256)
void gemm_tf32(const float* __restrict__ A, const float* __restrict__ B,
               const float* __restrict__ bias, float* __restrict__ C,
               int M, int N, int K)
{
    __shared__ float smem[2 * STAGE_FLOATS];

    const int tid  = threadIdx.x;
    const int wid  = tid >> 5;
    const int lane = tid & 31;
    const int warp_m = (wid & 1) * 64;
    const int warp_n = (wid >> 1) * 32;
    const int brow = blockIdx.y * 128;
    const int bcol = blockIdx.x * 128;
    const int lr = lane >> 2;
    const int lc = lane & 3;

    float acc[4][4][4];
#pragma unroll
    for (int mt = 0; mt < 4; mt++)
#pragma unroll
        for (int nt = 0; nt < 4; nt++)
#pragma unroll
            for (int i = 0; i < 4; i++) acc[mt][nt][i] = 0.f;

    const int a_row0 = tid >> 2;
    const int a_col  = (tid & 3) * 4;
    const int b_row0 = tid >> 5;
    const int b_col  = (tid & 31) * 4;

    auto load_stage = [&](int s, int k0) {
        float* Asm = smem + s * STAGE_FLOATS;
        float* Bsm = Asm + 128 * AS_STRIDE;
#pragma unroll
        for (int it = 0; it < 2; it++) {
            int r = a_row0 + it * 64;
            cp_async16(&Asm[r * AS_STRIDE + a_col],
                       &A[(size_t)(brow + r) * K + k0 + a_col]);
        }
#pragma unroll
        for (int it = 0; it < 2; it++) {
            int r = b_row0 + it * 8;
            cp_async16(&Bsm[r * BS_STRIDE + b_col],
                       &B[(size_t)(k0 + r) * N + bcol + b_col]);
        }
        asm volatile("cp.async.commit_group;");
    };

    const int KT = K / 16;
    load_stage(0, 0);

    for (int kt = 0; kt < KT; kt++) {
        const int s = kt & 1;
        if (kt + 1 < KT) {
            load_stage(s ^ 1, (kt + 1) * 16);
            asm volatile("cp.async.wait_group 1;");
        } else {
            asm volatile("cp.async.wait_group 0;");
        }
        __syncthreads();

        const float* Asm = smem + s * STAGE_FLOATS;
        const float* Bsm = Asm + 128 * AS_STRIDE;

#pragma unroll
        for (int ks = 0; ks < 2; ks++) {
            const int k0 = ks * 8;
            unsigned af[4][4], bf[4][2];
#pragma unroll
            for (int mt = 0; mt < 4; mt++) {
                const float* ap = Asm + (warp_m + mt * 16 + lr) * AS_STRIDE + k0 + lc;
                af[mt][0] = cvt_tf32(ap[0]);
                af[mt][1] = cvt_tf32(ap[8 * AS_STRIDE]);
                af[mt][2] = cvt_tf32(ap[4]);
                af[mt][3] = cvt_tf32(ap[8 * AS_STRIDE + 4]);
            }
#pragma unroll
            for (int nt = 0; nt < 4; nt++) {
                const float* bp = Bsm + (k0 + lc) * BS_STRIDE + warp_n + nt * 8 + lr;
                bf[nt][0] = cvt_tf32(bp[0]);
                bf[nt][1] = cvt_tf32(bp[4 * BS_STRIDE]);
            }
#pragma unroll
            for (int mt = 0; mt < 4; mt++)
#pragma unroll
                for (int nt = 0; nt < 4; nt++)
                    mma_tf32(acc[mt][nt][0], acc[mt][nt][1], acc[mt][nt][2], acc[mt][nt][3],
                             af[mt][0], af[mt][1], af[mt][2], af[mt][3],
                             bf[nt][0], bf[nt][1]);
        }
        __syncthreads();
    }

#pragma unroll
    for (int mt = 0; mt < 4; mt++) {
#pragma unroll
        for (int nt = 0; nt < 4; nt++) {
            const int row0 = brow + warp_m + mt * 16 + lr;
            const int col  = bcol + warp_n + nt * 8 + lc * 2;
            const float b0 = bias ? bias[col]     : 0.f;
            const float b1 = bias ? bias[col + 1] : 0.f;
            float2 v0 = make_float2(acc[mt][nt][0] + b0, acc[mt][nt][1] + b1);
            float2 v1 = make_float2(acc[mt][nt][2] + b0, acc[mt][nt][3] + b1);
            *(float2*)&C[(size_t)row0 * N + col]       = v0;
            *(float2*)&C[(size_t)(row0 + 8) * N + col] = v1;
        }
    }
}

// ---------------------------------------------------------------------------
// RoPE (unchanged)
// ---------------------------------------------------------------------------
__global__ __launch_bounds__(128)
void rope_kernel(float* __restrict__ Q, float* __restrict__ K,
                 const int* __restrict__ pos_ids)
{
    const int row  = blockIdx.x;
    const int head = blockIdx.y;
    const int d    = threadIdx.x;

    const int pos = pos_ids[row];
    const int i = d & 63;
    const float inv_freq = exp2f(-(float)(2 * i) * (1.0f / 128.0f) * 13.28771238f);
    const float ang = (float)pos * inv_freq;
    float c, s;
    sincosf(ang, &s, &c);

    float* base = (head < NH_)
        ? (Q + (size_t)row * QN_ + head * HD_)
        : (K + (size_t)row * KN_ + (head - NH_) * HD_);

    const float x = base[d];
    const float other = (d < 64) ? -base[d + 64] : base[d - 64];
    const float v = x * c + other * s;
    __syncthreads();
    base[d] = v;
}

// ---------------------------------------------------------------------------
// Tensor-core flash attention, bf16x3 error-compensated (hi/lo splits).
// Block: 64 queries x (b,h); 4 warps, each warp owns 16 query rows.
// Key tiles of 64. K/V staged in one smem union as bf16 hi/lo.
// ---------------------------------------------------------------------------
#define BQ 64
#define BK 64
#define KSTR 136   // bf16 row stride (128 + 8 pad): conflict-free frag loads

__device__ __forceinline__ void mma_bf16(float c[4], const unsigned a[4],
                                         unsigned b0, unsigned b1)
{
    asm volatile(
        "mma.sync.aligned.m16n8k16.row.col.f32.bf16.bf16.f32 "
        "{%0,%1,%2,%3}, {%4,%5,%6,%7}, {%8,%9}, {%0,%1,%2,%3};"
        : "+f"(c[0]), "+f"(c[1]), "+f"(c[2]), "+f"(c[3])
        : "r"(a[0]), "r"(a[1]), "r"(a[2]), "r"(a[3]), "r"(b0), "r"(b1));
}

__device__ __forceinline__ void ldsm4t(unsigned r[4], const void* p)
{
    unsigned a = (unsigned)__cvta_generic_to_shared(p);
    asm volatile(
        "ldmatrix.sync.aligned.m8n8.x4.trans.shared.b16 {%0,%1,%2,%3}, [%4];"
        : "=r"(r[0]), "=r"(r[1]), "=r"(r[2]), "=r"(r[3]) : "r"(a));
}

// split (x,y) into packed bf16 hi and lo (x in low half)
__device__ __forceinline__ void split2(float x, float y, unsigned& hi, unsigned& lo)
{
    __nv_bfloat162 h = __floats2bfloat162_rn(x, y);
    float hx = __bfloat162float(h.x), hy = __bfloat162float(h.y);
    __nv_bfloat162 l = __floats2bfloat162_rn(x - hx, y - hy);
    hi = *(unsigned*)&h;
    lo = *(unsigned*)&l;
}

__device__ __forceinline__ void store_split4(__nv_bfloat16* hi, __nv_bfloat16* lo, float4 v)
{
    __nv_bfloat162 h01 = __floats2bfloat162_rn(v.x, v.y);
    __nv_bfloat162 h23 = __floats2bfloat162_rn(v.z, v.w);
    __nv_bfloat162 l01 = __floats2bfloat162_rn(v.x - __bfloat162float(h01.x),
                                               v.y - __bfloat162float(h01.y));
    __nv_bfloat162 l23 = __floats2bfloat162_rn(v.z - __bfloat162float(h23.x),
                                               v.w - __bfloat162float(h23.y));
    *(__nv_bfloat162*)(hi)     = h01;
    *(__nv_bfloat162*)(hi + 2) = h23;
    *(__nv_bfloat162*)(lo)     = l01;
    *(__nv_bfloat162*)(lo + 2) = l23;
}

__global__ __launch_bounds__(128, 1)
void attn_mma(const float* __restrict__ Q, const float* __restrict__ K,
              const float* __restrict__ V, float* __restrict__ O)
{
    __shared__ __align__(16) __nv_bfloat16 s_hi[BK][KSTR];
    __shared__ __align__(16) __nv_bfloat16 s_lo[BK][KSTR];

    const int qt = blockIdx.x, h = blockIdx.y, b = blockIdx.z;
    const int q0 = qt * BQ;
    const int kvh = h >> 2;
    const int tid = threadIdx.x;
    const int w = tid >> 5, lane = tid & 31;
    const int lr = lane >> 2, lc = lane & 3;

    const int qrow0 = q0 + w * 16 + lr;
    const int qrow1 = qrow0 + 8;
    const float scale = 0.08838834764831845f;

    // ---- Q fragments (scaled, hi/lo split), resident in registers ----
    unsigned qa_hi[8][4], qa_lo[8][4];
    {
        const float* Q0 = Q + ((size_t)(b * S_) + qrow0) * QN_ + h * HD_;
        const float* Q1 = Q + ((size_t)(b * S_) + qrow1) * QN_ + h * HD_;
#pragma unroll
        for (int kt = 0; kt < 8; kt++) {
            float2 v;
            v = *(const float2*)(Q0 + kt * 16 + 2 * lc);
            split2(v.x * scale, v.y * scale, qa_hi[kt][0], qa_lo[kt][0]);
            v = *(const float2*)(Q1 + kt * 16 + 2 * lc);
            split2(v.x * scale, v.y * scale, qa_hi[kt][1], qa_lo[kt][1]);
            v = *(const float2*)(Q0 + kt * 16 + 2 * lc + 8);
            split2(v.x * scale, v.y * scale, qa_hi[kt][2], qa_lo[kt][2]);
            v = *(const float2*)(Q1 + kt * 16 + 2 * lc + 8);
            split2(v.x * scale, v.y * scale, qa_hi[kt][3], qa_lo[kt][3]);
        }
    }

    float m0 = -1e30f, m1 = -1e30f, l0 = 0.f, l1 = 0.f;
    float o[16][4];
#pragma unroll
    for (int i = 0; i < 16; i++)
#pragma unroll
        for (int j = 0; j < 4; j++) o[i][j] = 0.f;

    const int nTiles = q0 / BK + 1;
    const int wEnd = q0 + w * 16 + 16;   // exclusive key bound for this warp
    const int ldr = (lane & 7) + ((lane >> 3) & 1) * 8;  // ldmatrix row within 16
    const int ldc = ((lane >> 4) & 1) * 8;               // ldmatrix col offset

    for (int kt = 0; kt < nTiles; kt++) {
        const int kbase = kt * BK;
        const bool active = kbase < wEnd;

        __syncthreads();
        // ---- load K tile -> smem hi/lo ----
        {
            const float* src = K + ((size_t)(b * S_) + kbase) * KN_ + kvh * HD_;
            const int col = (tid & 31) * 4;
#pragma unroll
            for (int i = 0; i < 16; i++) {
                const int row = (tid >> 5) + i * 4;
                float4 v = *(const float4*)(src + (size_t)row * KN_ + col);
                store_split4(&s_hi[row][col], &s_lo[row][col], v);
            }
        }
        __syncthreads();

        float sA[8][4];
        unsigned pa_hi[4][4], pa_lo[4][4];

        if (active) {
#pragma unroll
            for (int nt = 0; nt < 8; nt++)
#pragma unroll
                for (int j = 0; j < 4; j++) sA[nt][j] = 0.f;

#pragma unroll
            for (int dkt = 0; dkt < 8; dkt++) {
#pragma unroll
                for (int nt = 0; nt < 8; nt++) {
                    const __nv_bfloat16* kh = &s_hi[nt * 8 + lr][dkt * 16 + 2 * lc];
                    const __nv_bfloat16* kl = &s_lo[nt * 8 + lr][dkt * 16 + 2 * lc];
                    unsigned bh0 = *(const unsigned*)kh;
                    unsigned bh1 = *(const unsigned*)(kh + 8);
                    unsigned bl0 = *(const unsigned*)kl;
                    unsigned bl1 = *(const unsigned*)(kl + 8);
                    mma_bf16(sA[nt], qa_hi[dkt], bh0, bh1);
                    mma_bf16(sA[nt], qa_hi[dkt], bl0, bl1);
                    mma_bf16(sA[nt], qa_lo[dkt], bh0, bh1);
                }
            }

            // causal mask (diagonal tiles only)
            if (kbase + BK > qrow0) {
#pragma unroll
                for (int nt = 0; nt < 8; nt++) {
                    const int j0 = kbase + nt * 8 + 2 * lc;
                    if (j0 > qrow0)     sA[nt][0] = -1e30f;
                    if (j0 + 1 > qrow0) sA[nt][1] = -1e30f;
                    if (j0 > qrow1)     sA[nt][2] = -1e30f;
                    if (j0 + 1 > qrow1) sA[nt][3] = -1e30f;
                }
            }

            // online softmax
            float mt0 = -1e30f, mt1 = -1e30f;
#pragma unroll
            for (int nt = 0; nt < 8; nt++) {
                mt0 = fmaxf(mt0, fmaxf(sA[nt][0], sA[nt][1]));
                mt1 = fmaxf(mt1, fmaxf(sA[nt][2], sA[nt][3]));
            }
            mt0 = fmaxf(mt0, __shfl_xor_sync(0xffffffffu, mt0, 1));
            mt0 = fmaxf(mt0, __shfl_xor_sync(0xffffffffu, mt0, 2));
            mt1 = fmaxf(mt1, __shfl_xor_sync(0xffffffffu, mt1, 1));
            mt1 = fmaxf(mt1, __shfl_xor_sync(0xffffffffu, mt1, 2));

            const float nm0 = fmaxf(m0, mt0);
            const float nm1 = fmaxf(m1, mt1);
            const float al0 = __expf(m0 - nm0);
            const float al1 = __expf(m1 - nm1);

            float rs0 = 0.f, rs1 = 0.f;
#pragma unroll
            for (int nt = 0; nt < 8; nt++) {
                sA[nt][0] = __expf(sA[nt][0] - nm0);
                sA[nt][1] = __expf(sA[nt][1] - nm0);
                sA[nt][2] = __expf(sA[nt][2] - nm1);
                sA[nt][3] = __expf(sA[nt][3] - nm1);
                rs0 += sA[nt][0] + sA[nt][1];
                rs1 += sA[nt][2] + sA[nt][3];
            }
            rs0 += __shfl_xor_sync(0xffffffffu, rs0, 1);
            rs0 += __shfl_xor_sync(0xffffffffu, rs0, 2);
            rs1 += __shfl_xor_sync(0xffffffffu, rs1, 1);
            rs1 += __shfl_xor_sync(0xffffffffu, rs1, 2);

            l0 = l0 * al0 + rs0;
            l1 = l1 * al1 + rs1;
            m0 = nm0; m1 = nm1;

#pragma unroll
            for (int i = 0; i < 16; i++) {
                o[i][0] *= al0; o[i][1] *= al0;
                o[i][2] *= al1; o[i][3] *= al1;
            }

            // P -> A-fragments (bf16 hi/lo)
#pragma unroll
            for (int t = 0; t < 4; t++) {
                split2(sA[2 * t][0],     sA[2 * t][1],     pa_hi[t][0], pa_lo[t][0]);
                split2(sA[2 * t][2],     sA[2 * t][3],     pa_hi[t][1], pa_lo[t][1]);
                split2(sA[2 * t + 1][0], sA[2 * t + 1][1], pa_hi[t][2], pa_lo[t][2]);
                split2(sA[2 * t + 1][2], sA[2 * t + 1][3], pa_hi[t][3], pa_lo[t][3]);
            }
        }

        __syncthreads();
        // ---- load V tile -> smem hi/lo (overwrites K) ----
        {
            const float* src = V + ((size_t)(b * S_) + kbase) * KN_ + kvh * HD_;
            const int col = (tid & 31) * 4;
#pragma unroll
            for (int i = 0; i < 16; i++) {
                const int row = (tid >> 5) + i * 4;
                float4 v = *(const float4*)(src + (size_t)row * KN_ + col);
                store_split4(&s_hi[row][col], &s_lo[row][col], v);
            }
        }
        __syncthreads();

        if (active) {
#pragma unroll
            for (int t = 0; t < 4; t++) {
#pragma unroll
                for (int np = 0; np < 8; np++) {
                    unsigned vh[4], vl[4];
                    ldsm4t(vh, &s_hi[t * 16 + ldr][np * 16 + ldc]);
                    ldsm4t(vl, &s_lo[t * 16 + ldr][np * 16 + ldc]);
                    mma_bf16(o[2 * np],     pa_hi[t], vh[0], vh[1]);
                    mma_bf16(o[2 * np],     pa_hi[t], vl[0], vl[1]);
                    mma_bf16(o[2 * np],     pa_lo[t], vh[0], vh[1]);
                    mma_bf16(o[2 * np + 1], pa_hi[t], vh[2], vh[3]);
                    mma_bf16(o[2 * np + 1], pa_hi[t], vl[2], vl[3]);
                    mma_bf16(o[2 * np + 1], pa_lo[t], vh[2], vh[3]);
                }
            }
        }
    }

    // epilogue
    const float il0 = 1.f / l0;
    const float il1 = 1.f / l1;
    float* O0 = O + ((size_t)(b * S_) + qrow0) * QN_ + h * HD_;
    float* O1 = O + ((size_t)(b * S_) + qrow1) * QN_ + h * HD_;
#pragma unroll
    for (int nt = 0; nt < 16; nt++) {
        *(float2*)(O0 + nt * 8 + 2 * lc) = make_float2(o[nt][0] * il0, o[nt][1] * il0);
        *(float2*)(O1 + nt * 8 + 2 * lc) = make_float2(o[nt][2] * il1, o[nt][3] * il1);
    }
}

// ---------------------------------------------------------------------------
// Launcher
// ---------------------------------------------------------------------------
extern "C" void kernel_launch(void* const* d_in, const int* in_sizes, int n_in,
                              void* d_out, int out_size)
{
    const float* X   = (const float*)d_in[0];
    const int*   pos = (const int*)  d_in[1];
    const float* Wq  = (const float*)d_in[2];
    const float* bq  = (const float*)d_in[3];
    const float* Wk  = (const float*)d_in[4];
    const float* bk  = (const float*)d_in[5];
    const float* Wv  = (const float*)d_in[6];
    const float* bv  = (const float*)d_in[7];
    const float* Wo  = (const float*)d_in[8];
    float* out = (float*)d_out;

    float *Qb, *Kb, *Vb, *AOb;
    cudaGetSymbolAddress((void**)&Qb,  g_Q);
    cudaGetSymbolAddress((void**)&Kb,  g_K);
    cudaGetSymbolAddress((void**)&Vb,  g_V);
    cudaGetSymbolAddress((void**)&AOb, g_AO);

    gemm_tf32<<<dim3(QN_ / 128, M_ / 128), 256>>>(X, Wq, bq, Qb, M_, QN_, H_);
    gemm_tf32<<<dim3(KN_ / 128, M_ / 128), 256>>>(X, Wk, bk, Kb, M_, KN_, H_);
    gemm_tf32<<<dim3(KN_ / 128, M_ / 128), 256>>>(X, Wv, bv, Vb, M_, KN_, H_);

    rope_kernel<<<dim3(M_, NH_ + NKV_), 128>>>(Qb, Kb, pos);

    attn_mma<<<dim3(S_ / BQ, NH_, B_), 128>>>(Qb, Kb, Vb, AOb);

    gemm_tf32<<<dim3(QN_ / 128, M_ / 128), 256>>>(AOb, Wo, nullptr, out, M_, QN_, H_);
}

// round 4
// speedup vs baseline: 4.4141x; 1.0809x over previous
#include <cuda_runtime.h>
#include <cuda_bf16.h>
#include <math.h>

// Problem constants
#define B_  2
#define S_  2048
#define H_  4096
#define NH_ 32
#define NKV_ 8
#define HD_ 128
#define M_  (B_ * S_)          // 4096 rows
#define QN_ (NH_ * HD_)        // 4096
#define KN_ (NKV_ * HD_)       // 1024

// Scratch (device globals; no allocations allowed)
__device__ float g_Q[M_ * QN_];    // 64 MB
__device__ float g_K[M_ * KN_];    // 16 MB
__device__ float g_V[M_ * KN_];    // 16 MB
__device__ float g_AO[M_ * QN_];   // 64 MB
// tf32-pre-rounded copies (so the GEMM needs no per-fragment CVT)
__device__ float g_Xr[M_ * H_];    // 64 MB
__device__ float g_Wq[H_ * QN_];   // 64 MB
__device__ float g_Wk[H_ * KN_];   // 16 MB
__device__ float g_Wv[H_ * KN_];   // 16 MB
__device__ float g_Wo[QN_ * H_];   // 64 MB

__device__ __forceinline__ float round_tf32_f(float f) {
    unsigned r;
    asm("cvt.rna.tf32.f32 %0, %1;" : "=r"(r) : "f"(f));
    return __uint_as_float(r);
}

// grid-stride pre-round: out[i] = tf32_rna(in[i])
__global__ __launch_bounds__(256)
void preround_kernel(const float* __restrict__ in, float* __restrict__ out, int n)
{
    int i = (blockIdx.x * 256 + threadIdx.x) * 4;
    const int stride = gridDim.x * 1024;
    for (; i < n; i += stride) {
        float4 v = *(const float4*)(in + i);
        v.x = round_tf32_f(v.x);
        v.y = round_tf32_f(v.y);
        v.z = round_tf32_f(v.z);
        v.w = round_tf32_f(v.w);
        *(float4*)(out + i) = v;
    }
}

// ---------------------------------------------------------------------------
// TF32 tensor-core GEMM: inputs are pre-rounded to tf32 grid -> raw-bit MMA.
// 128x128 block tile, 8 warps (each 64x32), k-tile 16, 2-stage cp.async.
// ---------------------------------------------------------------------------
#define AS_STRIDE 20
#define BS_STRIDE 136
#define STAGE_FLOATS (128 * AS_STRIDE + 16 * BS_STRIDE)

__device__ __forceinline__ void mma_tf32(float& d0, float& d1, float& d2, float& d3,
                                         unsigned a0, unsigned a1, unsigned a2, unsigned a3,
                                         unsigned b0, unsigned b1)
{
    asm volatile(
        "mma.sync.aligned.m16n8k8.row.col.f32.tf32.tf32.f32 "
        "{%0,%1,%2,%3}, {%4,%5,%6,%7}, {%8,%9}, {%0,%1,%2,%3};"
        : "+f"(d0), "+f"(d1), "+f"(d2), "+f"(d3)
        : "r"(a0), "r"(a1), "r"(a2), "r"(a3), "r"(b0), "r"(b1));
}

__device__ __forceinline__ void cp_async16(void* smem_dst, const void* gsrc) {
    unsigned dst = (unsigned)__cvta_generic_to_shared(smem_dst);
    asm volatile("cp.async.cg.shared.global [%0], [%1], 16;" :: "r"(dst), "l"(gsrc));
}

__global__ __launch_bounds__(256)
void gemm_tf32(const float* __restrict__ A, const float* __restrict__ B,
               const float* __restrict__ bias, float* __restrict__ C,
               int M, int N, int K)
{
    __shared__ float smem[2 * STAGE_FLOATS];

    const int tid  = threadIdx.x;
    const int wid  = tid >> 5;
    const int lane = tid & 31;
    const int warp_m = (wid & 1) * 64;
    const int warp_n = (wid >> 1) * 32;
    const int brow = blockIdx.y * 128;
    const int bcol = blockIdx.x * 128;
    const int lr = lane >> 2;
    const int lc = lane & 3;

    float acc[4][4][4];
#pragma unroll
    for (int mt = 0; mt < 4; mt++)
#pragma unroll
        for (int nt = 0; nt < 4; nt++)
#pragma unroll
            for (int i = 0; i < 4; i++) acc[mt][nt][i] = 0.f;

    const int a_row0 = tid >> 2;
    const int a_col  = (tid & 3) * 4;
    const int b_row0 = tid >> 5;
    const int b_col  = (tid & 31) * 4;

    auto load_stage = [&](int s, int k0) {
        float* Asm = smem + s * STAGE_FLOATS;
        float* Bsm = Asm + 128 * AS_STRIDE;
#pragma unroll
        for (int it = 0; it < 2; it++) {
            int r = a_row0 + it * 64;
            cp_async16(&Asm[r * AS_STRIDE + a_col],
                       &A[(size_t)(brow + r) * K + k0 + a_col]);
        }
#pragma unroll
        for (int it = 0; it < 2; it++) {
            int r = b_row0 + it * 8;
            cp_async16(&Bsm[r * BS_STRIDE + b_col],
                       &B[(size_t)(k0 + r) * N + bcol + b_col]);
        }
        asm volatile("cp.async.commit_group;");
    };

    const int KT = K / 16;
    load_stage(0, 0);

    for (int kt = 0; kt < KT; kt++) {
        const int s = kt & 1;
        if (kt + 1 < KT) {
            load_stage(s ^ 1, (kt + 1) * 16);
            asm volatile("cp.async.wait_group 1;");
        } else {
            asm volatile("cp.async.wait_group 0;");
        }
        __syncthreads();

        const float* Asm = smem + s * STAGE_FLOATS;
        const float* Bsm = Asm + 128 * AS_STRIDE;

#pragma unroll
        for (int ks = 0; ks < 2; ks++) {
            const int k0 = ks * 8;
            unsigned af[4][4], bf[4][2];
#pragma unroll
            for (int mt = 0; mt < 4; mt++) {
                const float* ap = Asm + (warp_m + mt * 16 + lr) * AS_STRIDE + k0 + lc;
                af[mt][0] = __float_as_uint(ap[0]);
                af[mt][1] = __float_as_uint(ap[8 * AS_STRIDE]);
                af[mt][2] = __float_as_uint(ap[4]);
                af[mt][3] = __float_as_uint(ap[8 * AS_STRIDE + 4]);
            }
#pragma unroll
            for (int nt = 0; nt < 4; nt++) {
                const float* bp = Bsm + (k0 + lc) * BS_STRIDE + warp_n + nt * 8 + lr;
                bf[nt][0] = __float_as_uint(bp[0]);
                bf[nt][1] = __float_as_uint(bp[4 * BS_STRIDE]);
            }
#pragma unroll
            for (int mt = 0; mt < 4; mt++)
#pragma unroll
                for (int nt = 0; nt < 4; nt++)
                    mma_tf32(acc[mt][nt][0], acc[mt][nt][1], acc[mt][nt][2], acc[mt][nt][3],
                             af[mt][0], af[mt][1], af[mt][2], af[mt][3],
                             bf[nt][0], bf[nt][1]);
        }
        __syncthreads();
    }

#pragma unroll
    for (int mt = 0; mt < 4; mt++) {
#pragma unroll
        for (int nt = 0; nt < 4; nt++) {
            const int row0 = brow + warp_m + mt * 16 + lr;
            const int col  = bcol + warp_n + nt * 8 + lc * 2;
            const float b0 = bias ? bias[col]     : 0.f;
            const float b1 = bias ? bias[col + 1] : 0.f;
            float2 v0 = make_float2(acc[mt][nt][0] + b0, acc[mt][nt][1] + b1);
            float2 v1 = make_float2(acc[mt][nt][2] + b0, acc[mt][nt][3] + b1);
            *(float2*)&C[(size_t)row0 * N + col]       = v0;
            *(float2*)&C[(size_t)(row0 + 8) * N + col] = v1;
        }
    }
}

// ---------------------------------------------------------------------------
// RoPE (unchanged)
// ---------------------------------------------------------------------------
__global__ __launch_bounds__(128)
void rope_kernel(float* __restrict__ Q, float* __restrict__ K,
                 const int* __restrict__ pos_ids)
{
    const int row  = blockIdx.x;
    const int head = blockIdx.y;
    const int d    = threadIdx.x;

    const int pos = pos_ids[row];
    const int i = d & 63;
    const float inv_freq = exp2f(-(float)(2 * i) * (1.0f / 128.0f) * 13.28771238f);
    const float ang = (float)pos * inv_freq;
    float c, s;
    sincosf(ang, &s, &c);

    float* base = (head < NH_)
        ? (Q + (size_t)row * QN_ + head * HD_)
        : (K + (size_t)row * KN_ + (head - NH_) * HD_);

    const float x = base[d];
    const float other = (d < 64) ? -base[d + 64] : base[d - 64];
    const float v = x * c + other * s;
    __syncthreads();
    base[d] = v;
}

// ---------------------------------------------------------------------------
// Tensor-core flash attention, bf16x3 error-compensated (unchanged core).
// Occupancy floor removed; epilogue pre-rounds AO to tf32 grid for O-GEMM.
// ---------------------------------------------------------------------------
#define BQ 64
#define BK 64
#define KSTR 136

__device__ __forceinline__ void mma_bf16(float c[4], const unsigned a[4],
                                         unsigned b0, unsigned b1)
{
    asm volatile(
        "mma.sync.aligned.m16n8k16.row.col.f32.bf16.bf16.f32 "
        "{%0,%1,%2,%3}, {%4,%5,%6,%7}, {%8,%9}, {%0,%1,%2,%3};"
        : "+f"(c[0]), "+f"(c[1]), "+f"(c[2]), "+f"(c[3])
        : "r"(a[0]), "r"(a[1]), "r"(a[2]), "r"(a[3]), "r"(b0), "r"(b1));
}

__device__ __forceinline__ void ldsm4t(unsigned r[4], const void* p)
{
    unsigned a = (unsigned)__cvta_generic_to_shared(p);
    asm volatile(
        "ldmatrix.sync.aligned.m8n8.x4.trans.shared.b16 {%0,%1,%2,%3}, [%4];"
        : "=r"(r[0]), "=r"(r[1]), "=r"(r[2]), "=r"(r[3]) : "r"(a));
}

__device__ __forceinline__ void split2(float x, float y, unsigned& hi, unsigned& lo)
{
    __nv_bfloat162 h = __floats2bfloat162_rn(x, y);
    float hx = __bfloat162float(h.x), hy = __bfloat162float(h.y);
    __nv_bfloat162 l = __floats2bfloat162_rn(x - hx, y - hy);
    hi = *(unsigned*)&h;
    lo = *(unsigned*)&l;
}

__device__ __forceinline__ void store_split4(__nv_bfloat16* hi, __nv_bfloat16* lo, float4 v)
{
    __nv_bfloat162 h01 = __floats2bfloat162_rn(v.x, v.y);
    __nv_bfloat162 h23 = __floats2bfloat162_rn(v.z, v.w);
    __nv_bfloat162 l01 = __floats2bfloat162_rn(v.x - __bfloat162float(h01.x),
                                               v.y - __bfloat162float(h01.y));
    __nv_bfloat162 l23 = __floats2bfloat162_rn(v.z - __bfloat162float(h23.x),
                                               v.w - __bfloat162float(h23.y));
    *(__nv_bfloat162*)(hi)     = h01;
    *(__nv_bfloat162*)(hi + 2) = h23;
    *(__nv_bfloat162*)(lo)     = l01;
    *(__nv_bfloat162*)(lo + 2) = l23;
}

__global__ __launch_bounds__(128)
void attn_mma(const float* __restrict__ Q, const float* __restrict__ K,
              const float* __restrict__ V, float* __restrict__ O)
{
    __shared__ __align__(16) __nv_bfloat16 s_hi[BK][KSTR];
    __shared__ __align__(16) __nv_bfloat16 s_lo[BK][KSTR];

    const int qt = blockIdx.x, h = blockIdx.y, b = blockIdx.z;
    const int q0 = qt * BQ;
    const int kvh = h >> 2;
    const int tid = threadIdx.x;
    const int w = tid >> 5, lane = tid & 31;
    const int lr = lane >> 2, lc = lane & 3;

    const int qrow0 = q0 + w * 16 + lr;
    const int qrow1 = qrow0 + 8;
    const float scale = 0.08838834764831845f;

    unsigned qa_hi[8][4], qa_lo[8][4];
    {
        const float* Q0 = Q + ((size_t)(b * S_) + qrow0) * QN_ + h * HD_;
        const float* Q1 = Q + ((size_t)(b * S_) + qrow1) * QN_ + h * HD_;
#pragma unroll
        for (int kt = 0; kt < 8; kt++) {
            float2 v;
            v = *(const float2*)(Q0 + kt * 16 + 2 * lc);
            split2(v.x * scale, v.y * scale, qa_hi[kt][0], qa_lo[kt][0]);
            v = *(const float2*)(Q1 + kt * 16 + 2 * lc);
            split2(v.x * scale, v.y * scale, qa_hi[kt][1], qa_lo[kt][1]);
            v = *(const float2*)(Q0 + kt * 16 + 2 * lc + 8);
            split2(v.x * scale, v.y * scale, qa_hi[kt][2], qa_lo[kt][2]);
            v = *(const float2*)(Q1 + kt * 16 + 2 * lc + 8);
            split2(v.x * scale, v.y * scale, qa_hi[kt][3], qa_lo[kt][3]);
        }
    }

    float m0 = -1e30f, m1 = -1e30f, l0 = 0.f, l1 = 0.f;
    float o[16][4];
#pragma unroll
    for (int i = 0; i < 16; i++)
#pragma unroll
        for (int j = 0; j < 4; j++) o[i][j] = 0.f;

    const int nTiles = q0 / BK + 1;
    const int wEnd = q0 + w * 16 + 16;
    const int ldr = (lane & 7) + ((lane >> 3) & 1) * 8;
    const int ldc = ((lane >> 4) & 1) * 8;

    for (int kt = 0; kt < nTiles; kt++) {
        const int kbase = kt * BK;
        const bool active = kbase < wEnd;

        __syncthreads();
        {
            const float* src = K + ((size_t)(b * S_) + kbase) * KN_ + kvh * HD_;
            const int col = (tid & 31) * 4;
#pragma unroll
            for (int i = 0; i < 16; i++) {
                const int row = (tid >> 5) + i * 4;
                float4 v = *(const float4*)(src + (size_t)row * KN_ + col);
                store_split4(&s_hi[row][col], &s_lo[row][col], v);
            }
        }
        __syncthreads();

        float sA[8][4];
        unsigned pa_hi[4][4], pa_lo[4][4];

        if (active) {
#pragma unroll
            for (int nt = 0; nt < 8; nt++)
#pragma unroll
                for (int j = 0; j < 4; j++) sA[nt][j] = 0.f;

#pragma unroll
            for (int dkt = 0; dkt < 8; dkt++) {
#pragma unroll
                for (int nt = 0; nt < 8; nt++) {
                    const __nv_bfloat16* kh = &s_hi[nt * 8 + lr][dkt * 16 + 2 * lc];
                    const __nv_bfloat16* kl = &s_lo[nt * 8 + lr][dkt * 16 + 2 * lc];
                    unsigned bh0 = *(const unsigned*)kh;
                    unsigned bh1 = *(const unsigned*)(kh + 8);
                    unsigned bl0 = *(const unsigned*)kl;
                    unsigned bl1 = *(const unsigned*)(kl + 8);
                    mma_bf16(sA[nt], qa_hi[dkt], bh0, bh1);
                    mma_bf16(sA[nt], qa_hi[dkt], bl0, bl1);
                    mma_bf16(sA[nt], qa_lo[dkt], bh0, bh1);
                }
            }

            if (kbase + BK > qrow0) {
#pragma unroll
                for (int nt = 0; nt < 8; nt++) {
                    const int j0 = kbase + nt * 8 + 2 * lc;
                    if (j0 > qrow0)     sA[nt][0] = -1e30f;
                    if (j0 + 1 > qrow0) sA[nt][1] = -1e30f;
                    if (j0 > qrow1)     sA[nt][2] = -1e30f;
                    if (j0 + 1 > qrow1) sA[nt][3] = -1e30f;
                }
            }

            float mt0 = -1e30f, mt1 = -1e30f;
#pragma unroll
            for (int nt = 0; nt < 8; nt++) {
                mt0 = fmaxf(mt0, fmaxf(sA[nt][0], sA[nt][1]));
                mt1 = fmaxf(mt1, fmaxf(sA[nt][2], sA[nt][3]));
            }
            mt0 = fmaxf(mt0, __shfl_xor_sync(0xffffffffu, mt0, 1));
            mt0 = fmaxf(mt0, __shfl_xor_sync(0xffffffffu, mt0, 2));
            mt1 = fmaxf(mt1, __shfl_xor_sync(0xffffffffu, mt1, 1));
            mt1 = fmaxf(mt1, __shfl_xor_sync(0xffffffffu, mt1, 2));

            const float nm0 = fmaxf(m0, mt0);
            const float nm1 = fmaxf(m1, mt1);
            const float al0 = __expf(m0 - nm0);
            const float al1 = __expf(m1 - nm1);

            float rs0 = 0.f, rs1 = 0.f;
#pragma unroll
            for (int nt = 0; nt < 8; nt++) {
                sA[nt][0] = __expf(sA[nt][0] - nm0);
                sA[nt][1] = __expf(sA[nt][1] - nm0);
                sA[nt][2] = __expf(sA[nt][2] - nm1);
                sA[nt][3] = __expf(sA[nt][3] - nm1);
                rs0 += sA[nt][0] + sA[nt][1];
                rs1 += sA[nt][2] + sA[nt][3];
            }
            rs0 += __shfl_xor_sync(0xffffffffu, rs0, 1);
            rs0 += __shfl_xor_sync(0xffffffffu, rs0, 2);
            rs1 += __shfl_xor_sync(0xffffffffu, rs1, 1);
            rs1 += __shfl_xor_sync(0xffffffffu, rs1, 2);

            l0 = l0 * al0 + rs0;
            l1 = l1 * al1 + rs1;
            m0 = nm0; m1 = nm1;

#pragma unroll
            for (int i = 0; i < 16; i++) {
                o[i][0] *= al0; o[i][1] *= al0;
                o[i][2] *= al1; o[i][3] *= al1;
            }

#pragma unroll
            for (int t = 0; t < 4; t++) {
                split2(sA[2 * t][0],     sA[2 * t][1],     pa_hi[t][0], pa_lo[t][0]);
                split2(sA[2 * t][2],     sA[2 * t][3],     pa_hi[t][1], pa_lo[t][1]);
                split2(sA[2 * t + 1][0], sA[2 * t + 1][1], pa_hi[t][2], pa_lo[t][2]);
                split2(sA[2 * t + 1][2], sA[2 * t + 1][3], pa_hi[t][3], pa_lo[t][3]);
            }
        }

        __syncthreads();
        {
            const float* src = V + ((size_t)(b * S_) + kbase) * KN_ + kvh * HD_;
            const int col = (tid & 31) * 4;
#pragma unroll
            for (int i = 0; i < 16; i++) {
                const int row = (tid >> 5) + i * 4;
                float4 v = *(const float4*)(src + (size_t)row * KN_ + col);
                store_split4(&s_hi[row][col], &s_lo[row][col], v);
            }
        }
        __syncthreads();

        if (active) {
#pragma unroll
            for (int t = 0; t < 4; t++) {
#pragma unroll
                for (int np = 0; np < 8; np++) {
                    unsigned vh[4], vl[4];
                    ldsm4t(vh, &s_hi[t * 16 + ldr][np * 16 + ldc]);
                    ldsm4t(vl, &s_lo[t * 16 + ldr][np * 16 + ldc]);
                    mma_bf16(o[2 * np],     pa_hi[t], vh[0], vh[1]);
                    mma_bf16(o[2 * np],     pa_hi[t], vl[0], vl[1]);
                    mma_bf16(o[2 * np],     pa_lo[t], vh[0], vh[1]);
                    mma_bf16(o[2 * np + 1], pa_hi[t], vh[2], vh[3]);
                    mma_bf16(o[2 * np + 1], pa_hi[t], vl[2], vl[3]);
                    mma_bf16(o[2 * np + 1], pa_lo[t], vh[2], vh[3]);
                }
            }
        }
    }

    // epilogue: normalize + pre-round to tf32 grid (feeds O-GEMM raw-bit MMA)
    const float il0 = 1.f / l0;
    const float il1 = 1.f / l1;
    float* O0 = O + ((size_t)(b * S_) + qrow0) * QN_ + h * HD_;
    float* O1 = O + ((size_t)(b * S_) + qrow1) * QN_ + h * HD_;
#pragma unroll
    for (int nt = 0; nt < 16; nt++) {
        *(float2*)(O0 + nt * 8 + 2 * lc) =
            make_float2(round_tf32_f(o[nt][0] * il0), round_tf32_f(o[nt][1] * il0));
        *(float2*)(O1 + nt * 8 + 2 * lc) =
            make_float2(round_tf32_f(o[nt][2] * il1), round_tf32_f(o[nt][3] * il1));
    }
}

// ---------------------------------------------------------------------------
// Launcher
// ---------------------------------------------------------------------------
extern "C" void kernel_launch(void* const* d_in, const int* in_sizes, int n_in,
                              void* d_out, int out_size)
{
    const float* X   = (const float*)d_in[0];
    const int*   pos = (const int*)  d_in[1];
    const float* Wq  = (const float*)d_in[2];
    const float* bq  = (const float*)d_in[3];
    const float* Wk  = (const float*)d_in[4];
    const float* bk  = (const float*)d_in[5];
    const float* Wv  = (const float*)d_in[6];
    const float* bv  = (const float*)d_in[7];
    const float* Wo  = (const float*)d_in[8];
    float* out = (float*)d_out;

    float *Qb, *Kb, *Vb, *AOb, *Xr, *Wqr, *Wkr, *Wvr, *Wor;
    cudaGetSymbolAddress((void**)&Qb,  g_Q);
    cudaGetSymbolAddress((void**)&Kb,  g_K);
    cudaGetSymbolAddress((void**)&Vb,  g_V);
    cudaGetSymbolAddress((void**)&AOb, g_AO);
    cudaGetSymbolAddress((void**)&Xr,  g_Xr);
    cudaGetSymbolAddress((void**)&Wqr, g_Wq);
    cudaGetSymbolAddress((void**)&Wkr, g_Wk);
    cudaGetSymbolAddress((void**)&Wvr, g_Wv);
    cudaGetSymbolAddress((void**)&Wor, g_Wo);

    // Pre-round inputs to the tf32 grid (removes CVT from GEMM inner loops)
    const int PR_BLOCKS = 1184;  // 8 blocks/SM
    preround_kernel<<<PR_BLOCKS, 256>>>(X,  Xr,  M_ * H_);
    preround_kernel<<<PR_BLOCKS, 256>>>(Wq, Wqr, H_ * QN_);
    preround_kernel<<<PR_BLOCKS, 256>>>(Wk, Wkr, H_ * KN_);
    preround_kernel<<<PR_BLOCKS, 256>>>(Wv, Wvr, H_ * KN_);
    preround_kernel<<<PR_BLOCKS, 256>>>(Wo, Wor, QN_ * H_);

    gemm_tf32<<<dim3(QN_ / 128, M_ / 128), 256>>>(Xr, Wqr, bq, Qb, M_, QN_, H_);
    gemm_tf32<<<dim3(KN_ / 128, M_ / 128), 256>>>(Xr, Wkr, bk, Kb, M_, KN_, H_);
    gemm_tf32<<<dim3(KN_ / 128, M_ / 128), 256>>>(Xr, Wvr, bv, Vb, M_, KN_, H_);

    rope_kernel<<<dim3(M_, NH_ + NKV_), 128>>>(Qb, Kb, pos);

    attn_mma<<<dim3(S_ / BQ, NH_, B_), 128>>>(Qb, Kb, Vb, AOb);

    gemm_tf32<<<dim3(QN_ / 128, M_ / 128), 256>>>(AOb, Wor, nullptr, out, M_, QN_, H_);
}